// round 3
// baseline (speedup 1.0000x reference)
#include <cuda_runtime.h>
#include <math.h>
#include <stdint.h>

#define DIMS   2560
#define NH     32
#define HD     80
#define SEQ    2048
#define QKV_N  (3*DIMS)

typedef unsigned long long u64;

// ---------------- f32x2 packed math helpers (sm_103a) -----------------------
__device__ __forceinline__ u64 pack2(float lo, float hi) {
    u64 r; asm("mov.b64 %0, {%1, %2};" : "=l"(r) : "f"(lo), "f"(hi)); return r;
}
__device__ __forceinline__ float2 unpack2(u64 v) {
    float2 f; asm("mov.b64 {%0, %1}, %2;" : "=f"(f.x), "=f"(f.y) : "l"(v)); return f;
}
__device__ __forceinline__ void fma2(u64& d, u64 a, u64 b) {
    asm("fma.rn.f32x2 %0, %1, %2, %0;" : "+l"(d) : "l"(a), "l"(b));
}
__device__ __forceinline__ void mul2(u64& d, u64 a) {
    asm("mul.rn.f32x2 %0, %0, %1;" : "+l"(d) : "l"(a));
}

// ---------------- scratch (static device globals; no runtime allocation) ----
__device__ float g_qkv [SEQ * QKV_N];   // [t][3*DIMS]  q|k|v
__device__ float g_attn[SEQ * DIMS];    // attention output, pre out-proj

// ============================================================================
// GEMM: C[M,N] = A[M,K] @ B[N,K]^T + bias[N]
// 128x128 block tile, BK=16, 256 threads, 8x8 microtile, f32x2 packed FMA.
// Accumulators paired along i (rows): acc2[p][j] = {C[2p][j], C[2p+1][j]}.
// ============================================================================
#define BM 128
#define BN 128
#define BK 16

__global__ __launch_bounds__(256) void gemm_tn_bias(
    const float* __restrict__ A,
    const float* __restrict__ B,
    const float* __restrict__ bias,
    float* __restrict__ C,
    int M, int N, int K)
{
    __shared__ __align__(16) float As[BK][BM + 4];
    __shared__ __align__(16) float Bs[BK][BN + 4];

    const int bm  = blockIdx.y * BM;
    const int bn  = blockIdx.x * BN;
    const int tid = threadIdx.x;
    const int tx  = tid & 15;
    const int ty  = tid >> 4;

    u64 acc2[4][8];
#pragma unroll
    for (int p = 0; p < 4; p++)
#pragma unroll
        for (int j = 0; j < 8; j++) acc2[p][j] = 0ull;

    const int lr = tid >> 2;          // 0..63
    const int lc = (tid & 3) << 2;    // 0,4,8,12

    const float* Aptr = A + (size_t)(bm + lr) * K + lc;
    const float* Bptr = B + (size_t)(bn + lr) * K + lc;

    for (int k0 = 0; k0 < K; k0 += BK) {
#pragma unroll
        for (int i = 0; i < 2; i++) {
            float4 v = *(const float4*)(Aptr + (size_t)i * 64 * K + k0);
            int r = lr + i * 64;
            As[lc + 0][r] = v.x; As[lc + 1][r] = v.y;
            As[lc + 2][r] = v.z; As[lc + 3][r] = v.w;
        }
#pragma unroll
        for (int i = 0; i < 2; i++) {
            float4 v = *(const float4*)(Bptr + (size_t)i * 64 * K + k0);
            int r = lr + i * 64;
            Bs[lc + 0][r] = v.x; Bs[lc + 1][r] = v.y;
            Bs[lc + 2][r] = v.z; Bs[lc + 3][r] = v.w;
        }
        __syncthreads();

#pragma unroll
        for (int k = 0; k < BK; k++) {
            // row pairs read directly as packed f32x2
            ulonglong2 aa0 = *(const ulonglong2*)&As[k][ty * 8 + 0];
            ulonglong2 aa1 = *(const ulonglong2*)&As[k][ty * 8 + 4];
            u64 a2[4] = {aa0.x, aa0.y, aa1.x, aa1.y};

            float4 b0 = *(const float4*)&Bs[k][tx * 8 + 0];
            float4 b1 = *(const float4*)&Bs[k][tx * 8 + 4];
            u64 bb[8];
            bb[0] = pack2(b0.x, b0.x); bb[1] = pack2(b0.y, b0.y);
            bb[2] = pack2(b0.z, b0.z); bb[3] = pack2(b0.w, b0.w);
            bb[4] = pack2(b1.x, b1.x); bb[5] = pack2(b1.y, b1.y);
            bb[6] = pack2(b1.z, b1.z); bb[7] = pack2(b1.w, b1.w);

#pragma unroll
            for (int p = 0; p < 4; p++)
#pragma unroll
                for (int j = 0; j < 8; j++)
                    fma2(acc2[p][j], a2[p], bb[j]);
        }
        __syncthreads();
    }

    // epilogue: unpack pairs, add bias, store float4
#pragma unroll
    for (int p = 0; p < 4; p++) {
        float r0v[8], r1v[8];
#pragma unroll
        for (int j = 0; j < 8; j++) {
            float2 v = unpack2(acc2[p][j]);
            r0v[j] = v.x; r1v[j] = v.y;
        }
        const int row0 = bm + ty * 8 + 2 * p;
#pragma unroll
        for (int j = 0; j < 8; j += 4) {
            const int col = bn + tx * 8 + j;
            float4 o0, o1;
            o0.x = r0v[j+0] + bias[col+0]; o0.y = r0v[j+1] + bias[col+1];
            o0.z = r0v[j+2] + bias[col+2]; o0.w = r0v[j+3] + bias[col+3];
            o1.x = r1v[j+0] + bias[col+0]; o1.y = r1v[j+1] + bias[col+1];
            o1.z = r1v[j+2] + bias[col+2]; o1.w = r1v[j+3] + bias[col+3];
            *(float4*)&C[(size_t)row0       * N + col] = o0;
            *(float4*)&C[(size_t)(row0 + 1) * N + col] = o1;
        }
    }
}

// ============================================================================
// RoPE on q and k (first 32 dims of each 80-dim head), in place.
// ============================================================================
__global__ void rope_kernel(float* __restrict__ qkv)
{
    int idx = blockIdx.x * blockDim.x + threadIdx.x;      // SEQ*NH*16 total
    if (idx >= SEQ * NH * 16) return;
    const int d = idx & 15;
    const int h = (idx >> 4) & 31;
    const int t = idx >> 9;

    const float freq  = __expf(-(float)d * 0.5756462732485115f); // ln(1e4)/16
    const float theta = (float)t * freq;
    float s, c;
    sincosf(theta, &s, &c);

    size_t base = (size_t)t * QKV_N + h * HD;
    {
        float x1 = qkv[base + d], x2 = qkv[base + d + 16];
        qkv[base + d]      = x1 * c - x2 * s;
        qkv[base + d + 16] = x1 * s + x2 * c;
    }
    base += DIMS;
    {
        float x1 = qkv[base + d], x2 = qkv[base + d + 16];
        qkv[base + d]      = x1 * c - x2 * s;
        qkv[base + d + 16] = x1 * s + x2 * c;
    }
}

// ============================================================================
// Flash attention, fp32, causal, f32x2 packed FMA in QK and PV loops.
// One block = (head, 64-query tile). smem layout as before.
// ============================================================================
#define QS_OFF   0
#define KS_OFF   5120
#define VS_OFF   10240
#define PS_OFF   15872
#define RED_OFF  20224
#define M_OFF    20480
#define L_OFF    20544
#define AL_OFF   20608
#define ATT_SMEM_BYTES (20672 * 4)

__global__ __launch_bounds__(256) void attn_kernel(
    const float* __restrict__ qkv, float* __restrict__ out)
{
    extern __shared__ __align__(16) float sm[];
    float* Qs   = sm + QS_OFF;
    float* Ks   = sm + KS_OFF;
    float* Vs   = sm + VS_OFF;
    float* Ps   = sm + PS_OFF;
    float* red  = sm + RED_OFF;
    float* mrow = sm + M_OFF;
    float* lrow = sm + L_OFF;
    float* arow = sm + AL_OFF;

    const int h   = blockIdx.x;
    const int qb  = blockIdx.y;
    const int tid = threadIdx.x;
    const int q0  = qb * 64;

    // ---- load Q tile transposed: Qs[d][r] ----
    {
        const int r  = tid >> 2;
        const int dq = (tid & 3) * 20;
        const float* src = qkv + (size_t)(q0 + r) * QKV_N + h * HD + dq;
#pragma unroll
        for (int u = 0; u < 5; u++) {
            float4 v = *(const float4*)(src + u * 4);
            const int d = dq + u * 4;
            Qs[(d + 0) * 64 + r] = v.x; Qs[(d + 1) * 64 + r] = v.y;
            Qs[(d + 2) * 64 + r] = v.z; Qs[(d + 3) * 64 + r] = v.w;
        }
    }

    // PV mapping: 2 rows x 10 cols per thread (even col base for f32x2)
    const int rp = (tid >> 3) * 2;    // row base: 0,2,...,62
    const int cp = (tid & 7) * 10;    // col base: 0,10,...,70 (even)
    u64 o2[2][5];
#pragma unroll
    for (int i = 0; i < 2; i++)
#pragma unroll
        for (int j = 0; j < 5; j++) o2[i][j] = 0ull;

    if (tid < 64) { mrow[tid] = -3.0e38f; lrow[tid] = 0.f; }
    __syncthreads();

    const float scale = 0.11180339887498949f;   // 1/sqrt(80)
    const int ntiles = qb + 1;

    for (int kb = 0; kb < ntiles; kb++) {
        const int k0 = kb * 64;

        // ---- load K tile transposed + V tile ----
        {
            const int r  = tid >> 2;
            const int dq = (tid & 3) * 20;
            const float* ksrc = qkv + DIMS   + (size_t)(k0 + r) * QKV_N + h * HD + dq;
            const float* vsrc = qkv + 2*DIMS + (size_t)(k0 + r) * QKV_N + h * HD + dq;
#pragma unroll
            for (int u = 0; u < 5; u++) {
                float4 v = *(const float4*)(ksrc + u * 4);
                const int d = dq + u * 4;
                Ks[(d + 0) * 64 + r] = v.x; Ks[(d + 1) * 64 + r] = v.y;
                Ks[(d + 2) * 64 + r] = v.z; Ks[(d + 3) * 64 + r] = v.w;
            }
#pragma unroll
            for (int u = 0; u < 5; u++) {
                *(float4*)&Vs[r * 88 + dq + u * 4] = *(const float4*)(vsrc + u * 4);
            }
        }
        __syncthreads();

        // ---- S = Q K^T : 4 q-rows x 4 key-cols, keys paired in f32x2 ----
        const int sx = (tid & 15) * 4;   // key cols (16B aligned)
        const int sy = (tid >> 4) * 4;   // q rows
        u64 s2[4][2];
#pragma unroll
        for (int i = 0; i < 4; i++) { s2[i][0] = 0ull; s2[i][1] = 0ull; }

#pragma unroll 4
        for (int d = 0; d < HD; d++) {
            float4 qv = *(const float4*)&Qs[d * 64 + sy];
            ulonglong2 kk = *(const ulonglong2*)&Ks[d * 64 + sx];
            u64 q2[4];
            q2[0] = pack2(qv.x, qv.x); q2[1] = pack2(qv.y, qv.y);
            q2[2] = pack2(qv.z, qv.z); q2[3] = pack2(qv.w, qv.w);
#pragma unroll
            for (int i = 0; i < 4; i++) {
                fma2(s2[i][0], q2[i], kk.x);
                fma2(s2[i][1], q2[i], kk.y);
            }
        }

        // write transposed (masked + scaled): Ps[key][row]
#pragma unroll
        for (int i = 0; i < 4; i++) {
            const int grow = q0 + sy + i;
            float2 sA = unpack2(s2[i][0]);   // cols sx+0, sx+1
            float2 sB = unpack2(s2[i][1]);   // cols sx+2, sx+3
            float sv[4] = {sA.x, sA.y, sB.x, sB.y};
#pragma unroll
            for (int j = 0; j < 4; j++) {
                const int gcol = k0 + sx + j;
                float val = (gcol <= grow) ? sv[j] * scale : -1.0e30f;
                Ps[(sx + j) * 68 + (sy + i)] = val;
            }
        }
        __syncthreads();

        // ---- online softmax ----
        {   // partial row max
            const int r = tid >> 2, seg = tid & 3;
            float mx = -3.0e38f;
            const int c0 = seg * 16;
#pragma unroll
            for (int c = 0; c < 16; c++) mx = fmaxf(mx, Ps[(c0 + c) * 68 + r]);
            red[r * 4 + seg] = mx;
        }
        __syncthreads();
        if (tid < 64) {
            float mt = fmaxf(fmaxf(red[tid*4+0], red[tid*4+1]),
                             fmaxf(red[tid*4+2], red[tid*4+3]));
            float mo = mrow[tid];
            float mn = fmaxf(mo, mt);
            float al = __expf(mo - mn);
            mrow[tid] = mn; arow[tid] = al; lrow[tid] *= al;
        }
        __syncthreads();
        {   // exponentiate + partial sums
            const int r = tid >> 2, seg = tid & 3;
            const float mn = mrow[r];
            const int c0 = seg * 16;
            float ss = 0.f;
#pragma unroll
            for (int c = 0; c < 16; c++) {
                float e = __expf(Ps[(c0 + c) * 68 + r] - mn);
                Ps[(c0 + c) * 68 + r] = e;
                ss += e;
            }
            red[r * 4 + seg] = ss;
        }
        __syncthreads();
        if (tid < 64)
            lrow[tid] += red[tid*4+0] + red[tid*4+1] + red[tid*4+2] + red[tid*4+3];

        // ---- rescale O, accumulate P V (d-dim paired in f32x2) ----
        {
            u64 al0 = pack2(arow[rp],     arow[rp]);
            u64 al1 = pack2(arow[rp + 1], arow[rp + 1]);
#pragma unroll
            for (int j = 0; j < 5; j++) { mul2(o2[0][j], al0); mul2(o2[1][j], al1); }
        }

#pragma unroll 4
        for (int c = 0; c < 64; c++) {
            // probs for the two rows, loaded as one packed pair then broadcast
            float2 pp = unpack2(*(const u64*)&Ps[c * 68 + rp]);
            u64 p0 = pack2(pp.x, pp.x);
            u64 p1 = pack2(pp.y, pp.y);
#pragma unroll
            for (int j = 0; j < 5; j++) {
                u64 vv = *(const u64*)&Vs[c * 88 + cp + 2 * j];
                fma2(o2[0][j], p0, vv);
                fma2(o2[1][j], p1, vv);
            }
        }
        __syncthreads();   // protect Ks/Vs/Ps for next tile; also orders lrow
    }

    // ---- epilogue ----
    {
        float inv0 = 1.f / lrow[rp];
        float inv1 = 1.f / lrow[rp + 1];
        float* dst0 = out + (size_t)(q0 + rp)     * DIMS + h * HD + cp;
        float* dst1 = out + (size_t)(q0 + rp + 1) * DIMS + h * HD + cp;
#pragma unroll
        for (int j = 0; j < 5; j++) {
            float2 v0 = unpack2(o2[0][j]);
            float2 v1 = unpack2(o2[1][j]);
            v0.x *= inv0; v0.y *= inv0;
            v1.x *= inv1; v1.y *= inv1;
            *(float2*)(dst0 + 2 * j) = v0;
            *(float2*)(dst1 + 2 * j) = v1;
        }
    }
}

// ============================================================================
extern "C" void kernel_launch(void* const* d_in, const int* in_sizes, int n_in,
                              void* d_out, int out_size)
{
    const float* x       = (const float*)d_in[0];
    const float* Wqkv_w  = (const float*)d_in[1];
    const float* Wqkv_b  = (const float*)d_in[2];
    const float* out_w   = (const float*)d_in[3];
    const float* out_b   = (const float*)d_in[4];
    // d_in[5] = mask: causal triu(-1e9), implemented structurally; unused.
    float* outp = (float*)d_out;

    float *qkv_ptr = nullptr, *attn_ptr = nullptr;
    cudaGetSymbolAddress((void**)&qkv_ptr,  g_qkv);
    cudaGetSymbolAddress((void**)&attn_ptr, g_attn);

    cudaFuncSetAttribute(attn_kernel,
                         cudaFuncAttributeMaxDynamicSharedMemorySize,
                         ATT_SMEM_BYTES);

    // 1) QKV projection
    {
        dim3 grid(QKV_N / BN, SEQ / BM);
        gemm_tn_bias<<<grid, 256>>>(x, Wqkv_w, Wqkv_b, qkv_ptr, SEQ, QKV_N, DIMS);
    }
    // 2) RoPE on q,k
    {
        int total = SEQ * NH * 16;
        rope_kernel<<<(total + 255) / 256, 256>>>(qkv_ptr);
    }
    // 3) causal flash attention
    {
        dim3 grid(NH, SEQ / 64);
        attn_kernel<<<grid, 256, ATT_SMEM_BYTES>>>(qkv_ptr, attn_ptr);
    }
    // 4) output projection
    {
        dim3 grid(DIMS / BN, SEQ / BM);
        gemm_tn_bias<<<grid, 256>>>(attn_ptr, out_w, out_b, outp, SEQ, DIMS, DIMS);
    }
}

// round 5
// speedup vs baseline: 1.8694x; 1.8694x over previous
#include <cuda_runtime.h>
#include <cuda_bf16.h>
#include <math.h>
#include <stdint.h>

#define DIMS   2560
#define NH     32
#define HD     80
#define SEQ    2048
#define QKV_N  (3*DIMS)

// ---------------- scratch (static device globals; no runtime allocation) ----
__device__ float g_qkv [SEQ * QKV_N];          // [t][3*DIMS]  q|k|v (fp32)
__device__ float g_attn[SEQ * DIMS];           // attention out (fp32)

__device__ __nv_bfloat16 g_xhi [SEQ * DIMS];
__device__ __nv_bfloat16 g_xlo [SEQ * DIMS];
__device__ __nv_bfloat16 g_w1hi[QKV_N * DIMS];
__device__ __nv_bfloat16 g_w1lo[QKV_N * DIMS];
__device__ __nv_bfloat16 g_w2hi[DIMS * DIMS];
__device__ __nv_bfloat16 g_w2lo[DIMS * DIMS];
__device__ __nv_bfloat16 g_ahi [SEQ * DIMS];
__device__ __nv_bfloat16 g_alo [SEQ * DIMS];

// ============================================================================
// fp32 -> bf16 hi/lo split conversion (vectorized, memory bound)
// ============================================================================
__global__ void cvt_hilo_kernel(const float* __restrict__ src,
                                __nv_bfloat16* __restrict__ hi,
                                __nv_bfloat16* __restrict__ lo, int n4)
{
    int i = blockIdx.x * blockDim.x + threadIdx.x;
    if (i >= n4) return;
    float4 v = ((const float4*)src)[i];
    union { __nv_bfloat16 b[4]; uint2 u; } H, L;
    H.b[0] = __float2bfloat16(v.x); L.b[0] = __float2bfloat16(v.x - __bfloat162float(H.b[0]));
    H.b[1] = __float2bfloat16(v.y); L.b[1] = __float2bfloat16(v.y - __bfloat162float(H.b[1]));
    H.b[2] = __float2bfloat16(v.z); L.b[2] = __float2bfloat16(v.z - __bfloat162float(H.b[2]));
    H.b[3] = __float2bfloat16(v.w); L.b[3] = __float2bfloat16(v.w - __bfloat162float(H.b[3]));
    ((uint2*)hi)[i] = H.u;
    ((uint2*)lo)[i] = L.u;
}

// ============================================================================
// PTX helpers (all baseline compute_103-safe: sm_80-era instructions)
// ============================================================================
__device__ __forceinline__ uint32_t smem_u32(const void* p){
    uint32_t a;
    asm("{ .reg .u64 t; cvta.to.shared.u64 t, %1; cvt.u32.u64 %0, t; }"
        : "=r"(a) : "l"(p));
    return a;
}
__device__ __forceinline__ void cp16(uint32_t dst, const void* src){
    asm volatile("cp.async.ca.shared.global [%0], [%1], 16;"
                 :: "r"(dst), "l"(src) : "memory");
}
__device__ __forceinline__ void cp_commit(){
    asm volatile("cp.async.commit_group;" ::: "memory");
}
template<int N> __device__ __forceinline__ void cp_wait(){
    asm volatile("cp.async.wait_group %0;" :: "n"(N) : "memory");
}
__device__ __forceinline__ void ldm_x4(uint32_t a, uint32_t& r0, uint32_t& r1,
                                       uint32_t& r2, uint32_t& r3){
    asm volatile("ldmatrix.sync.aligned.m8n8.x4.shared.b16 {%0,%1,%2,%3}, [%4];"
                 : "=r"(r0), "=r"(r1), "=r"(r2), "=r"(r3) : "r"(a));
}
__device__ __forceinline__ void mma_bf16(float* c, const uint32_t* a,
                                         uint32_t b0, uint32_t b1){
    asm volatile(
      "mma.sync.aligned.m16n8k16.row.col.f32.bf16.bf16.f32 "
      "{%0,%1,%2,%3}, {%4,%5,%6,%7}, {%8,%9}, {%0,%1,%2,%3};"
      : "+f"(c[0]), "+f"(c[1]), "+f"(c[2]), "+f"(c[3])
      : "r"(a[0]), "r"(a[1]), "r"(a[2]), "r"(a[3]), "r"(b0), "r"(b1));
}

// ============================================================================
// bf16x3 tensor-core GEMM:  C[M,N] = A[M,K] @ B[N,K]^T + bias
//   A,B given as hi/lo bf16 pairs.  C = Ahi*Bhi + Ahi*Blo + Alo*Bhi.
// 128x128 CTA tile, 8 warps each 32x64, BK=32, cp.async double buffer.
// smem rows pitched to 80 bytes (40 bf16): conflict-free ldmatrix.
// ============================================================================
#define GBM 128
#define GBN 128
#define GBK 32
#define ROWP 40                 // bf16 units per smem row (80 bytes)
#define TILE_B (128 * ROWP * 2) // 10240 bytes per tile buffer
#define STAGE_B (4 * TILE_B)    // Ahi, Alo, Bhi, Blo
#define GM_SMEM (2 * STAGE_B)   // 81920 bytes

__global__ __launch_bounds__(256, 2) void gemm_bf16x3(
    const __nv_bfloat16* __restrict__ Ahi, const __nv_bfloat16* __restrict__ Alo,
    const __nv_bfloat16* __restrict__ Bhi, const __nv_bfloat16* __restrict__ Blo,
    const float* __restrict__ bias, float* __restrict__ C,
    int M, int N, int K)
{
    extern __shared__ __align__(16) char smem[];
    const uint32_t sb = smem_u32(smem);

    const int tid  = threadIdx.x;
    const int wid  = tid >> 5;
    const int lane = tid & 31;
    const int bm   = blockIdx.y * GBM;
    const int bn   = blockIdx.x * GBN;
    const int wm   = (wid & 3) * 32;     // warp M offset
    const int wn   = (wid >> 2) * 64;    // warp N offset

    // ---- async stage loader: 4 tiles x 512 16B-transactions, 8 per thread
    const int ltile = tid >> 6;            // 0:Ahi 1:Alo 2:Bhi 3:Blo
    const int lbase = tid & 63;
    const __nv_bfloat16* gsrc =
        (ltile == 0) ? Ahi + (size_t)bm * K :
        (ltile == 1) ? Alo + (size_t)bm * K :
        (ltile == 2) ? Bhi + (size_t)bn * K :
                       Blo + (size_t)bn * K;

    auto load_stage = [&](int s, int k0){
        const uint32_t dstb = sb + s * STAGE_B + ltile * TILE_B;
#pragma unroll
        for (int i = 0; i < 8; i++) {
            const int idx = lbase + i * 64;
            const int row = idx >> 2;
            const int kq  = idx & 3;
            cp16(dstb + row * 80 + kq * 16,
                 gsrc + (size_t)row * K + k0 + kq * 8);
        }
        cp_commit();
    };

    float acc[2][8][4];
#pragma unroll
    for (int mt = 0; mt < 2; mt++)
#pragma unroll
        for (int nt = 0; nt < 8; nt++)
#pragma unroll
            for (int r = 0; r < 4; r++) acc[mt][nt][r] = 0.f;

    const int nchunks = K / GBK;
    load_stage(0, 0);

    // ldmatrix lane addressing (byte offsets within a tile buffer)
    const int a_row = lane & 15;
    const int a_koff = (lane >> 4) << 3;
    const int b_row = (lane & 7) + ((lane >> 4) << 3);
    const int b_koff = ((lane >> 3) & 1) << 3;

    for (int ic = 0; ic < nchunks; ic++) {
        if (ic + 1 < nchunks) load_stage((ic + 1) & 1, (ic + 1) * GBK);
        if (ic + 1 < nchunks) cp_wait<1>(); else cp_wait<0>();
        __syncthreads();

        const uint32_t st = sb + (ic & 1) * STAGE_B;
        const uint32_t sAhi = st;
        const uint32_t sAlo = st + TILE_B;
        const uint32_t sBhi = st + 2 * TILE_B;
        const uint32_t sBlo = st + 3 * TILE_B;

#pragma unroll
        for (int ks = 0; ks < 2; ks++) {
            const int kb = ks * 16;
            uint32_t ahi[2][4], alo[2][4];
#pragma unroll
            for (int mt = 0; mt < 2; mt++) {
                const uint32_t aoff =
                    (uint32_t)((wm + mt * 16 + a_row) * 80 + (kb + a_koff) * 2);
                ldm_x4(sAhi + aoff, ahi[mt][0], ahi[mt][1], ahi[mt][2], ahi[mt][3]);
                ldm_x4(sAlo + aoff, alo[mt][0], alo[mt][1], alo[mt][2], alo[mt][3]);
            }
#pragma unroll
            for (int np = 0; np < 4; np++) {
                const uint32_t boff =
                    (uint32_t)((wn + np * 16 + b_row) * 80 + (kb + b_koff) * 2);
                uint32_t bh0, bh1, bh2, bh3, bl0, bl1, bl2, bl3;
                ldm_x4(sBhi + boff, bh0, bh1, bh2, bh3);
                ldm_x4(sBlo + boff, bl0, bl1, bl2, bl3);
#pragma unroll
                for (int mt = 0; mt < 2; mt++) {
                    mma_bf16(acc[mt][2*np],   ahi[mt], bh0, bh1);
                    mma_bf16(acc[mt][2*np+1], ahi[mt], bh2, bh3);
                    mma_bf16(acc[mt][2*np],   ahi[mt], bl0, bl1);
                    mma_bf16(acc[mt][2*np+1], ahi[mt], bl2, bl3);
                    mma_bf16(acc[mt][2*np],   alo[mt], bh0, bh1);
                    mma_bf16(acc[mt][2*np+1], alo[mt], bh2, bh3);
                }
            }
        }
        __syncthreads();
    }

    // ---- epilogue: fragment -> global + bias
#pragma unroll
    for (int mt = 0; mt < 2; mt++) {
        const int r0 = bm + wm + mt * 16 + (lane >> 2);
#pragma unroll
        for (int nt = 0; nt < 8; nt++) {
            const int col = bn + wn + nt * 8 + ((lane & 3) << 1);
            const float2 bv = *(const float2*)&bias[col];
            float2 v0 = { acc[mt][nt][0] + bv.x, acc[mt][nt][1] + bv.y };
            float2 v1 = { acc[mt][nt][2] + bv.x, acc[mt][nt][3] + bv.y };
            *(float2*)&C[(size_t)r0       * N + col] = v0;
            *(float2*)&C[(size_t)(r0 + 8) * N + col] = v1;
        }
    }
}

// ============================================================================
// RoPE on q and k (first 32 dims of each 80-dim head), in place.
// ============================================================================
__global__ void rope_kernel(float* __restrict__ qkv)
{
    int idx = blockIdx.x * blockDim.x + threadIdx.x;      // SEQ*NH*16 total
    if (idx >= SEQ * NH * 16) return;
    const int d = idx & 15;
    const int h = (idx >> 4) & 31;
    const int t = idx >> 9;

    const float freq  = __expf(-(float)d * 0.5756462732485115f); // ln(1e4)/16
    const float theta = (float)t * freq;
    float s, c;
    sincosf(theta, &s, &c);

    size_t base = (size_t)t * QKV_N + h * HD;
    {
        float x1 = qkv[base + d], x2 = qkv[base + d + 16];
        qkv[base + d]      = x1 * c - x2 * s;
        qkv[base + d + 16] = x1 * s + x2 * c;
    }
    base += DIMS;
    {
        float x1 = qkv[base + d], x2 = qkv[base + d + 16];
        qkv[base + d]      = x1 * c - x2 * s;
        qkv[base + d + 16] = x1 * s + x2 * c;
    }
}

// ============================================================================
// Flash attention, fp32, causal (round-2 scalar version, known good).
// ============================================================================
#define QS_OFF   0
#define KS_OFF   5120
#define VS_OFF   10240
#define PS_OFF   15872
#define RED_OFF  20224
#define M_OFF    20480
#define L_OFF    20544
#define AL_OFF   20608
#define ATT_SMEM_BYTES (20672 * 4)

__global__ __launch_bounds__(256) void attn_kernel(
    const float* __restrict__ qkv, float* __restrict__ out)
{
    extern __shared__ float smf[];
    float* Qs   = smf + QS_OFF;
    float* Ks   = smf + KS_OFF;
    float* Vs   = smf + VS_OFF;
    float* Ps   = smf + PS_OFF;
    float* red  = smf + RED_OFF;
    float* mrow = smf + M_OFF;
    float* lrow = smf + L_OFF;
    float* arow = smf + AL_OFF;

    const int h   = blockIdx.x;
    const int qb  = blockIdx.y;
    const int tid = threadIdx.x;
    const int q0  = qb * 64;

    {
        const int r  = tid >> 2;
        const int dq = (tid & 3) * 20;
        const float* src = qkv + (size_t)(q0 + r) * QKV_N + h * HD + dq;
#pragma unroll
        for (int u = 0; u < 5; u++) {
            float4 v = *(const float4*)(src + u * 4);
            const int d = dq + u * 4;
            Qs[(d + 0) * 64 + r] = v.x; Qs[(d + 1) * 64 + r] = v.y;
            Qs[(d + 2) * 64 + r] = v.z; Qs[(d + 3) * 64 + r] = v.w;
        }
    }

    const int pr = (tid >> 4) * 4;
    const int pd = (tid & 15) * 5;
    float o[4][5];
#pragma unroll
    for (int i = 0; i < 4; i++)
#pragma unroll
        for (int j = 0; j < 5; j++) o[i][j] = 0.f;

    if (tid < 64) { mrow[tid] = -3.0e38f; lrow[tid] = 0.f; }
    __syncthreads();

    const float scale = 0.11180339887498949f;   // 1/sqrt(80)
    const int ntiles = qb + 1;

    for (int kb = 0; kb < ntiles; kb++) {
        const int k0 = kb * 64;
        {
            const int r  = tid >> 2;
            const int dq = (tid & 3) * 20;
            const float* ksrc = qkv + DIMS   + (size_t)(k0 + r) * QKV_N + h * HD + dq;
            const float* vsrc = qkv + 2*DIMS + (size_t)(k0 + r) * QKV_N + h * HD + dq;
#pragma unroll
            for (int u = 0; u < 5; u++) {
                float4 v = *(const float4*)(ksrc + u * 4);
                const int d = dq + u * 4;
                Ks[(d + 0) * 64 + r] = v.x; Ks[(d + 1) * 64 + r] = v.y;
                Ks[(d + 2) * 64 + r] = v.z; Ks[(d + 3) * 64 + r] = v.w;
            }
#pragma unroll
            for (int u = 0; u < 5; u++)
                *(float4*)&Vs[r * 88 + dq + u * 4] = *(const float4*)(vsrc + u * 4);
        }
        __syncthreads();

        const int sx = (tid & 15) * 4;
        const int sy = (tid >> 4) * 4;
        float s[4][4];
#pragma unroll
        for (int i = 0; i < 4; i++)
#pragma unroll
            for (int j = 0; j < 4; j++) s[i][j] = 0.f;

#pragma unroll 4
        for (int d = 0; d < HD; d++) {
            float4 qv = *(const float4*)&Qs[d * 64 + sy];
            float4 kv = *(const float4*)&Ks[d * 64 + sx];
            float qa[4] = {qv.x, qv.y, qv.z, qv.w};
            float ka[4] = {kv.x, kv.y, kv.z, kv.w};
#pragma unroll
            for (int i = 0; i < 4; i++)
#pragma unroll
                for (int j = 0; j < 4; j++)
                    s[i][j] = fmaf(qa[i], ka[j], s[i][j]);
        }

#pragma unroll
        for (int j = 0; j < 4; j++) {
            const int gcol = k0 + sx + j;
#pragma unroll
            for (int i = 0; i < 4; i++) {
                const int grow = q0 + sy + i;
                float val = (gcol <= grow) ? s[i][j] * scale : -1.0e30f;
                Ps[(sx + j) * 68 + (sy + i)] = val;
            }
        }
        __syncthreads();

        {
            const int r = tid >> 2, seg = tid & 3;
            float mx = -3.0e38f;
            const int c0 = seg * 16;
#pragma unroll
            for (int c = 0; c < 16; c++) mx = fmaxf(mx, Ps[(c0 + c) * 68 + r]);
            red[r * 4 + seg] = mx;
        }
        __syncthreads();
        if (tid < 64) {
            float mt = fmaxf(fmaxf(red[tid*4+0], red[tid*4+1]),
                             fmaxf(red[tid*4+2], red[tid*4+3]));
            float mo = mrow[tid];
            float mn = fmaxf(mo, mt);
            float al = __expf(mo - mn);
            mrow[tid] = mn; arow[tid] = al; lrow[tid] *= al;
        }
        __syncthreads();
        {
            const int r = tid >> 2, seg = tid & 3;
            const float mn = mrow[r];
            const int c0 = seg * 16;
            float ss = 0.f;
#pragma unroll
            for (int c = 0; c < 16; c++) {
                float e = __expf(Ps[(c0 + c) * 68 + r] - mn);
                Ps[(c0 + c) * 68 + r] = e;
                ss += e;
            }
            red[r * 4 + seg] = ss;
        }
        __syncthreads();
        if (tid < 64)
            lrow[tid] += red[tid*4+0] + red[tid*4+1] + red[tid*4+2] + red[tid*4+3];

        float al[4];
#pragma unroll
        for (int i = 0; i < 4; i++) al[i] = arow[pr + i];
#pragma unroll
        for (int i = 0; i < 4; i++)
#pragma unroll
            for (int j = 0; j < 5; j++) o[i][j] *= al[i];

#pragma unroll 4
        for (int c = 0; c < 64; c++) {
            float4 p4 = *(const float4*)&Ps[c * 68 + pr];
            float pv[4] = {p4.x, p4.y, p4.z, p4.w};
#pragma unroll
            for (int j = 0; j < 5; j++) {
                float v = Vs[c * 88 + pd + j];
#pragma unroll
                for (int i = 0; i < 4; i++)
                    o[i][j] = fmaf(pv[i], v, o[i][j]);
            }
        }
        __syncthreads();
    }

    float inv[4];
#pragma unroll
    for (int i = 0; i < 4; i++) inv[i] = 1.f / lrow[pr + i];
#pragma unroll
    for (int i = 0; i < 4; i++) {
        const int row = q0 + pr + i;
#pragma unroll
        for (int j = 0; j < 5; j++)
            out[(size_t)row * DIMS + h * HD + pd + j] = o[i][j] * inv[i];
    }
}

// ============================================================================
extern "C" void kernel_launch(void* const* d_in, const int* in_sizes, int n_in,
                              void* d_out, int out_size)
{
    const float* x       = (const float*)d_in[0];
    const float* Wqkv_w  = (const float*)d_in[1];
    const float* Wqkv_b  = (const float*)d_in[2];
    const float* out_w   = (const float*)d_in[3];
    const float* out_b   = (const float*)d_in[4];
    // d_in[5] = mask: causal triu(-1e9), implemented structurally; unused.
    float* outp = (float*)d_out;

    float *qkv_ptr = nullptr, *attn_ptr = nullptr;
    __nv_bfloat16 *xhi, *xlo, *w1hi, *w1lo, *w2hi, *w2lo, *ahi, *alo;
    cudaGetSymbolAddress((void**)&qkv_ptr,  g_qkv);
    cudaGetSymbolAddress((void**)&attn_ptr, g_attn);
    cudaGetSymbolAddress((void**)&xhi,  g_xhi);  cudaGetSymbolAddress((void**)&xlo,  g_xlo);
    cudaGetSymbolAddress((void**)&w1hi, g_w1hi); cudaGetSymbolAddress((void**)&w1lo, g_w1lo);
    cudaGetSymbolAddress((void**)&w2hi, g_w2hi); cudaGetSymbolAddress((void**)&w2lo, g_w2lo);
    cudaGetSymbolAddress((void**)&ahi,  g_ahi);  cudaGetSymbolAddress((void**)&alo,  g_alo);

    cudaFuncSetAttribute(gemm_bf16x3,
                         cudaFuncAttributeMaxDynamicSharedMemorySize, GM_SMEM);
    cudaFuncSetAttribute(attn_kernel,
                         cudaFuncAttributeMaxDynamicSharedMemorySize, ATT_SMEM_BYTES);

    // 0) split-precision conversions of x and weights
    {
        int n4 = (SEQ * DIMS) / 4;
        cvt_hilo_kernel<<<(n4 + 255) / 256, 256>>>(x, xhi, xlo, n4);
        n4 = (QKV_N * DIMS) / 4;
        cvt_hilo_kernel<<<(n4 + 255) / 256, 256>>>(Wqkv_w, w1hi, w1lo, n4);
        n4 = (DIMS * DIMS) / 4;
        cvt_hilo_kernel<<<(n4 + 255) / 256, 256>>>(out_w, w2hi, w2lo, n4);
    }
    // 1) QKV projection (bf16x3 tensor cores)
    {
        dim3 grid(QKV_N / GBN, SEQ / GBM);
        gemm_bf16x3<<<grid, 256, GM_SMEM>>>(xhi, xlo, w1hi, w1lo,
                                            Wqkv_b, qkv_ptr, SEQ, QKV_N, DIMS);
    }
    // 2) RoPE on q,k
    {
        int total = SEQ * NH * 16;
        rope_kernel<<<(total + 255) / 256, 256>>>(qkv_ptr);
    }
    // 3) causal flash attention (SIMT fp32)
    {
        dim3 grid(NH, SEQ / 64);
        attn_kernel<<<grid, 256, ATT_SMEM_BYTES>>>(qkv_ptr, attn_ptr);
    }
    // 4) output projection (bf16x3 tensor cores)
    {
        int n4 = (SEQ * DIMS) / 4;
        cvt_hilo_kernel<<<(n4 + 255) / 256, 256>>>(attn_ptr, ahi, alo, n4);
        dim3 grid(DIMS / GBN, SEQ / GBM);
        gemm_bf16x3<<<grid, 256, GM_SMEM>>>(ahi, alo, w2hi, w2lo,
                                            out_b, outp, SEQ, DIMS, DIMS);
    }
}

// round 6
// speedup vs baseline: 2.8551x; 1.5273x over previous
#include <cuda_runtime.h>
#include <cuda_bf16.h>
#include <math.h>
#include <stdint.h>

#define DIMS   2560
#define NH     32
#define HD     80
#define SEQ    2048
#define QKV_N  (3*DIMS)

// ---------------- scratch (static device globals; no runtime allocation) ----
__device__ float g_qkv [SEQ * QKV_N];          // [t][3*DIMS]  q|k|v (fp32)

__device__ __nv_bfloat16 g_xhi [SEQ * DIMS];
__device__ __nv_bfloat16 g_xlo [SEQ * DIMS];
__device__ __nv_bfloat16 g_w1hi[QKV_N * DIMS];
__device__ __nv_bfloat16 g_w1lo[QKV_N * DIMS];
__device__ __nv_bfloat16 g_w2hi[DIMS * DIMS];
__device__ __nv_bfloat16 g_w2lo[DIMS * DIMS];
__device__ __nv_bfloat16 g_ahi [SEQ * DIMS];   // attention out hi/lo (bf16)
__device__ __nv_bfloat16 g_alo [SEQ * DIMS];
__device__ __nv_bfloat16 g_qkvhi[SEQ * QKV_N]; // post-rope qkv hi/lo (bf16)
__device__ __nv_bfloat16 g_qkvlo[SEQ * QKV_N];

// ============================================================================
// fp32 -> bf16 hi/lo split conversion (vectorized, memory bound)
// ============================================================================
__global__ void cvt_hilo_kernel(const float* __restrict__ src,
                                __nv_bfloat16* __restrict__ hi,
                                __nv_bfloat16* __restrict__ lo, int n4)
{
    int i = blockIdx.x * blockDim.x + threadIdx.x;
    if (i >= n4) return;
    float4 v = ((const float4*)src)[i];
    union { __nv_bfloat16 b[4]; uint2 u; } H, L;
    H.b[0] = __float2bfloat16(v.x); L.b[0] = __float2bfloat16(v.x - __bfloat162float(H.b[0]));
    H.b[1] = __float2bfloat16(v.y); L.b[1] = __float2bfloat16(v.y - __bfloat162float(H.b[1]));
    H.b[2] = __float2bfloat16(v.z); L.b[2] = __float2bfloat16(v.z - __bfloat162float(H.b[2]));
    H.b[3] = __float2bfloat16(v.w); L.b[3] = __float2bfloat16(v.w - __bfloat162float(H.b[3]));
    ((uint2*)hi)[i] = H.u;
    ((uint2*)lo)[i] = L.u;
}

// ============================================================================
// PTX helpers (all baseline compute_103-safe: sm_80-era instructions)
// ============================================================================
__device__ __forceinline__ uint32_t smem_u32(const void* p){
    uint32_t a;
    asm("{ .reg .u64 t; cvta.to.shared.u64 t, %1; cvt.u32.u64 %0, t; }"
        : "=r"(a) : "l"(p));
    return a;
}
__device__ __forceinline__ void cp16(uint32_t dst, const void* src){
    asm volatile("cp.async.ca.shared.global [%0], [%1], 16;"
                 :: "r"(dst), "l"(src) : "memory");
}
__device__ __forceinline__ void cp_commit(){
    asm volatile("cp.async.commit_group;" ::: "memory");
}
template<int N> __device__ __forceinline__ void cp_wait(){
    asm volatile("cp.async.wait_group %0;" :: "n"(N) : "memory");
}
__device__ __forceinline__ void ldm_x4(uint32_t a, uint32_t& r0, uint32_t& r1,
                                       uint32_t& r2, uint32_t& r3){
    asm volatile("ldmatrix.sync.aligned.m8n8.x4.shared.b16 {%0,%1,%2,%3}, [%4];"
                 : "=r"(r0), "=r"(r1), "=r"(r2), "=r"(r3) : "r"(a));
}
__device__ __forceinline__ void ldm_x4_t(uint32_t a, uint32_t& r0, uint32_t& r1,
                                         uint32_t& r2, uint32_t& r3){
    asm volatile("ldmatrix.sync.aligned.m8n8.x4.trans.shared.b16 {%0,%1,%2,%3}, [%4];"
                 : "=r"(r0), "=r"(r1), "=r"(r2), "=r"(r3) : "r"(a));
}
__device__ __forceinline__ void mma_bf16(float* c, const uint32_t* a,
                                         uint32_t b0, uint32_t b1){
    asm volatile(
      "mma.sync.aligned.m16n8k16.row.col.f32.bf16.bf16.f32 "
      "{%0,%1,%2,%3}, {%4,%5,%6,%7}, {%8,%9}, {%0,%1,%2,%3};"
      : "+f"(c[0]), "+f"(c[1]), "+f"(c[2]), "+f"(c[3])
      : "r"(a[0]), "r"(a[1]), "r"(a[2]), "r"(a[3]), "r"(b0), "r"(b1));
}
__device__ __forceinline__ uint32_t pkbf(__nv_bfloat16 a, __nv_bfloat16 b){
    union { __nv_bfloat16 h[2]; uint32_t u; } t;
    t.h[0] = a; t.h[1] = b;
    return t.u;
}

// ============================================================================
// bf16x3 tensor-core GEMM:  C[M,N] = A[M,K] @ B[N,K]^T + bias  (round-5, good)
// ============================================================================
#define GBM 128
#define GBN 128
#define GBK 32
#define ROWP 40
#define TILE_B (128 * ROWP * 2)
#define STAGE_B (4 * TILE_B)
#define GM_SMEM (2 * STAGE_B)

__global__ __launch_bounds__(256, 2) void gemm_bf16x3(
    const __nv_bfloat16* __restrict__ Ahi, const __nv_bfloat16* __restrict__ Alo,
    const __nv_bfloat16* __restrict__ Bhi, const __nv_bfloat16* __restrict__ Blo,
    const float* __restrict__ bias, float* __restrict__ C,
    int M, int N, int K)
{
    extern __shared__ __align__(16) char smem[];
    const uint32_t sb = smem_u32(smem);

    const int tid  = threadIdx.x;
    const int wid  = tid >> 5;
    const int lane = tid & 31;
    const int bm   = blockIdx.y * GBM;
    const int bn   = blockIdx.x * GBN;
    const int wm   = (wid & 3) * 32;
    const int wn   = (wid >> 2) * 64;

    const int ltile = tid >> 6;
    const int lbase = tid & 63;
    const __nv_bfloat16* gsrc =
        (ltile == 0) ? Ahi + (size_t)bm * K :
        (ltile == 1) ? Alo + (size_t)bm * K :
        (ltile == 2) ? Bhi + (size_t)bn * K :
                       Blo + (size_t)bn * K;

    auto load_stage = [&](int s, int k0){
        const uint32_t dstb = sb + s * STAGE_B + ltile * TILE_B;
#pragma unroll
        for (int i = 0; i < 8; i++) {
            const int idx = lbase + i * 64;
            const int row = idx >> 2;
            const int kq  = idx & 3;
            cp16(dstb + row * 80 + kq * 16,
                 gsrc + (size_t)row * K + k0 + kq * 8);
        }
        cp_commit();
    };

    float acc[2][8][4];
#pragma unroll
    for (int mt = 0; mt < 2; mt++)
#pragma unroll
        for (int nt = 0; nt < 8; nt++)
#pragma unroll
            for (int r = 0; r < 4; r++) acc[mt][nt][r] = 0.f;

    const int nchunks = K / GBK;
    load_stage(0, 0);

    const int a_row = lane & 15;
    const int a_koff = (lane >> 4) << 3;
    const int b_row = (lane & 7) + ((lane >> 4) << 3);
    const int b_koff = ((lane >> 3) & 1) << 3;

    for (int ic = 0; ic < nchunks; ic++) {
        if (ic + 1 < nchunks) load_stage((ic + 1) & 1, (ic + 1) * GBK);
        if (ic + 1 < nchunks) cp_wait<1>(); else cp_wait<0>();
        __syncthreads();

        const uint32_t st = sb + (ic & 1) * STAGE_B;
        const uint32_t sAhi = st;
        const uint32_t sAlo = st + TILE_B;
        const uint32_t sBhi = st + 2 * TILE_B;
        const uint32_t sBlo = st + 3 * TILE_B;

#pragma unroll
        for (int ks = 0; ks < 2; ks++) {
            const int kb = ks * 16;
            uint32_t ahi[2][4], alo[2][4];
#pragma unroll
            for (int mt = 0; mt < 2; mt++) {
                const uint32_t aoff =
                    (uint32_t)((wm + mt * 16 + a_row) * 80 + (kb + a_koff) * 2);
                ldm_x4(sAhi + aoff, ahi[mt][0], ahi[mt][1], ahi[mt][2], ahi[mt][3]);
                ldm_x4(sAlo + aoff, alo[mt][0], alo[mt][1], alo[mt][2], alo[mt][3]);
            }
#pragma unroll
            for (int np = 0; np < 4; np++) {
                const uint32_t boff =
                    (uint32_t)((wn + np * 16 + b_row) * 80 + (kb + b_koff) * 2);
                uint32_t bh0, bh1, bh2, bh3, bl0, bl1, bl2, bl3;
                ldm_x4(sBhi + boff, bh0, bh1, bh2, bh3);
                ldm_x4(sBlo + boff, bl0, bl1, bl2, bl3);
#pragma unroll
                for (int mt = 0; mt < 2; mt++) {
                    mma_bf16(acc[mt][2*np],   ahi[mt], bh0, bh1);
                    mma_bf16(acc[mt][2*np+1], ahi[mt], bh2, bh3);
                    mma_bf16(acc[mt][2*np],   ahi[mt], bl0, bl1);
                    mma_bf16(acc[mt][2*np+1], ahi[mt], bl2, bl3);
                    mma_bf16(acc[mt][2*np],   alo[mt], bh0, bh1);
                    mma_bf16(acc[mt][2*np+1], alo[mt], bh2, bh3);
                }
            }
        }
        __syncthreads();
    }

#pragma unroll
    for (int mt = 0; mt < 2; mt++) {
        const int r0 = bm + wm + mt * 16 + (lane >> 2);
#pragma unroll
        for (int nt = 0; nt < 8; nt++) {
            const int col = bn + wn + nt * 8 + ((lane & 3) << 1);
            const float2 bv = *(const float2*)&bias[col];
            float2 v0 = { acc[mt][nt][0] + bv.x, acc[mt][nt][1] + bv.y };
            float2 v1 = { acc[mt][nt][2] + bv.x, acc[mt][nt][3] + bv.y };
            *(float2*)&C[(size_t)r0       * N + col] = v0;
            *(float2*)&C[(size_t)(r0 + 8) * N + col] = v1;
        }
    }
}

// ============================================================================
// RoPE on q and k (first 32 dims of each 80-dim head), in place (fp32).
// ============================================================================
__global__ void rope_kernel(float* __restrict__ qkv)
{
    int idx = blockIdx.x * blockDim.x + threadIdx.x;      // SEQ*NH*16 total
    if (idx >= SEQ * NH * 16) return;
    const int d = idx & 15;
    const int h = (idx >> 4) & 31;
    const int t = idx >> 9;

    const float freq  = __expf(-(float)d * 0.5756462732485115f); // ln(1e4)/16
    const float theta = (float)t * freq;
    float s, c;
    sincosf(theta, &s, &c);

    size_t base = (size_t)t * QKV_N + h * HD;
    {
        float x1 = qkv[base + d], x2 = qkv[base + d + 16];
        qkv[base + d]      = x1 * c - x2 * s;
        qkv[base + d + 16] = x1 * s + x2 * c;
    }
    base += DIMS;
    {
        float x1 = qkv[base + d], x2 = qkv[base + d + 16];
        qkv[base + d]      = x1 * c - x2 * s;
        qkv[base + d + 16] = x1 * s + x2 * c;
    }
}

// ============================================================================
// Tensor-core flash attention, causal, bf16x3 (QK and PV both 3-term).
// 1 CTA = (head, 64 q-rows), 128 threads = 4 warps, each warp 16 q-rows.
// K/V single-buffered in smem; 2 CTAs/SM hide load and softmax latency.
// smem tiles (bf16, pitch 88): Qhi Qlo Khi Klo Vhi Vlo.
// ============================================================================
#define AP     88
#define SQ_HI  0
#define SQ_LO  (64*AP)
#define SK_HI  (2*64*AP)
#define SK_LO  (3*64*AP)
#define SV_HI  (4*64*AP)
#define SV_LO  (5*64*AP)
#define ATT_SMEM (6*64*AP*2)   // 67584 bytes

__global__ __launch_bounds__(128, 2) void attn_tc(
    const __nv_bfloat16* __restrict__ qkvhi,
    const __nv_bfloat16* __restrict__ qkvlo,
    __nv_bfloat16* __restrict__ ohi,
    __nv_bfloat16* __restrict__ olo)
{
    extern __shared__ __align__(16) __nv_bfloat16 smA[];
    const uint32_t sb = smem_u32(smA);
    const int h = blockIdx.x, qb = blockIdx.y;
    const int tid = threadIdx.x, lane = tid & 31, w = tid >> 5;
    const int q0 = qb * 64;
    const float scale = 0.11180339887498949f;   // 1/sqrt(80)

    // ---- load Q hi/lo via cp.async ----
    {
        const size_t off = (size_t)q0 * QKV_N + h * HD;
#pragma unroll
        for (int it = 0; it < 5; it++) {
            const int idx = it * 128 + tid;
            const int row = idx / 10, col = idx % 10;
            const size_t go = off + (size_t)row * QKV_N + col * 8;
            cp16(sb + (SQ_HI + row * AP) * 2 + col * 16, qkvhi + go);
            cp16(sb + (SQ_LO + row * AP) * 2 + col * 16, qkvlo + go);
        }
    }
    auto loadKV = [&](int kb){
        const size_t koff = (size_t)(kb * 64) * QKV_N + DIMS + h * HD;
#pragma unroll
        for (int it = 0; it < 5; it++) {
            const int idx = it * 128 + tid;
            const int row = idx / 10, col = idx % 10;
            const size_t gk = koff + (size_t)row * QKV_N + col * 8;
            const size_t gv = gk + DIMS;
            cp16(sb + (SK_HI + row * AP) * 2 + col * 16, qkvhi + gk);
            cp16(sb + (SK_LO + row * AP) * 2 + col * 16, qkvlo + gk);
            cp16(sb + (SV_HI + row * AP) * 2 + col * 16, qkvhi + gv);
            cp16(sb + (SV_LO + row * AP) * 2 + col * 16, qkvlo + gv);
        }
    };

    float of[10][4];
#pragma unroll
    for (int i = 0; i < 10; i++)
#pragma unroll
        for (int j = 0; j < 4; j++) of[i][j] = 0.f;
    float mA = -1e30f, mB = -1e30f, lA = 0.f, lB = 0.f;

    loadKV(0);
    cp_commit(); cp_wait<0>();
    __syncthreads();

    const int a_row  = lane & 15;
    const int a_k    = (lane >> 4) << 3;
    const int b_row  = (lane & 7) + ((lane >> 4) << 3);
    const int b_k    = ((lane >> 3) & 1) << 3;
    const int vk     = (lane & 7) + (((lane >> 3) & 1) << 3);
    const int vd     = (lane >> 4) << 3;
    const int clb    = 2 * (lane & 3);
    const int rl     = w * 16 + (lane >> 2);   // local q row (A); B = +8

    const int ntiles = qb + 1;
    for (int kb = 0; kb < ntiles; kb++) {
        // ---- S = Q K^T (bf16x3) ----
        float sf[8][4];
#pragma unroll
        for (int i = 0; i < 8; i++)
#pragma unroll
            for (int j = 0; j < 4; j++) sf[i][j] = 0.f;

#pragma unroll
        for (int kc = 0; kc < 5; kc++) {
            uint32_t ahi[4], alo[4];
            const uint32_t aoff = (uint32_t)((w * 16 + a_row) * AP + kc * 16 + a_k) * 2;
            ldm_x4(sb + SQ_HI * 2 + aoff, ahi[0], ahi[1], ahi[2], ahi[3]);
            ldm_x4(sb + SQ_LO * 2 + aoff, alo[0], alo[1], alo[2], alo[3]);
#pragma unroll
            for (int bp = 0; bp < 4; bp++) {
                const uint32_t boff = (uint32_t)((bp * 16 + b_row) * AP + kc * 16 + b_k) * 2;
                uint32_t bh0, bh1, bh2, bh3, bl0, bl1, bl2, bl3;
                ldm_x4(sb + SK_HI * 2 + boff, bh0, bh1, bh2, bh3);
                ldm_x4(sb + SK_LO * 2 + boff, bl0, bl1, bl2, bl3);
                mma_bf16(sf[2*bp],   ahi, bh0, bh1);
                mma_bf16(sf[2*bp+1], ahi, bh2, bh3);
                mma_bf16(sf[2*bp],   ahi, bl0, bl1);
                mma_bf16(sf[2*bp+1], ahi, bl2, bl3);
                mma_bf16(sf[2*bp],   alo, bh0, bh1);
                mma_bf16(sf[2*bp+1], alo, bh2, bh3);
            }
        }

        // ---- scale + causal mask (diag tile only) ----
        const bool diag = (kb == qb);
#pragma unroll
        for (int nt = 0; nt < 8; nt++) {
            const int c0 = nt * 8 + clb;
#pragma unroll
            for (int j = 0; j < 2; j++) {
                float vA = sf[nt][j]     * scale;
                float vB = sf[nt][2 + j] * scale;
                if (diag) {
                    if (c0 + j > rl)     vA = -1e30f;
                    if (c0 + j > rl + 8) vB = -1e30f;
                }
                sf[nt][j] = vA; sf[nt][2 + j] = vB;
            }
        }

        // ---- online softmax (register + quad shfl) ----
        float mxA = -1e30f, mxB = -1e30f;
#pragma unroll
        for (int nt = 0; nt < 8; nt++) {
            mxA = fmaxf(mxA, fmaxf(sf[nt][0], sf[nt][1]));
            mxB = fmaxf(mxB, fmaxf(sf[nt][2], sf[nt][3]));
        }
        mxA = fmaxf(mxA, __shfl_xor_sync(0xffffffffu, mxA, 1));
        mxA = fmaxf(mxA, __shfl_xor_sync(0xffffffffu, mxA, 2));
        mxB = fmaxf(mxB, __shfl_xor_sync(0xffffffffu, mxB, 1));
        mxB = fmaxf(mxB, __shfl_xor_sync(0xffffffffu, mxB, 2));
        const float mnA = fmaxf(mA, mxA), mnB = fmaxf(mB, mxB);
        const float alphaA = __expf(mA - mnA), alphaB = __expf(mB - mnB);
        mA = mnA; mB = mnB;

        float sA = 0.f, sB = 0.f;
#pragma unroll
        for (int nt = 0; nt < 8; nt++) {
#pragma unroll
            for (int j = 0; j < 2; j++) {
                float pA = __expf(sf[nt][j]     - mnA);
                float pB = __expf(sf[nt][2 + j] - mnB);
                sf[nt][j] = pA; sf[nt][2 + j] = pB;
                sA += pA; sB += pB;
            }
        }
        sA += __shfl_xor_sync(0xffffffffu, sA, 1);
        sA += __shfl_xor_sync(0xffffffffu, sA, 2);
        sB += __shfl_xor_sync(0xffffffffu, sB, 1);
        sB += __shfl_xor_sync(0xffffffffu, sB, 2);
        lA = lA * alphaA + sA;
        lB = lB * alphaB + sB;
#pragma unroll
        for (int d = 0; d < 10; d++) {
            of[d][0] *= alphaA; of[d][1] *= alphaA;
            of[d][2] *= alphaB; of[d][3] *= alphaB;
        }

        // ---- O += P V (bf16x3), P packed from S fragments in registers ----
#pragma unroll
        for (int kc2 = 0; kc2 < 4; kc2++) {
            uint32_t phi[4], plo[4];
#pragma unroll
            for (int half = 0; half < 2; half++) {
                const int nt = 2 * kc2 + half;
                const float v0 = sf[nt][0], v1 = sf[nt][1];
                const float v2 = sf[nt][2], v3 = sf[nt][3];
                __nv_bfloat16 h0 = __float2bfloat16(v0), h1 = __float2bfloat16(v1);
                __nv_bfloat16 h2 = __float2bfloat16(v2), h3 = __float2bfloat16(v3);
                phi[half * 2 + 0] = pkbf(h0, h1);     // rows A
                phi[half * 2 + 1] = pkbf(h2, h3);     // rows B
                plo[half * 2 + 0] = pkbf(__float2bfloat16(v0 - __bfloat162float(h0)),
                                         __float2bfloat16(v1 - __bfloat162float(h1)));
                plo[half * 2 + 1] = pkbf(__float2bfloat16(v2 - __bfloat162float(h2)),
                                         __float2bfloat16(v3 - __bfloat162float(h3)));
            }
            // reorder: a-frag = {rowsA klo, rowsB klo, rowsA khi, rowsB khi}
            uint32_t aH[4] = { phi[0], phi[1], phi[2], phi[3] };
            uint32_t aL[4] = { plo[0], plo[1], plo[2], plo[3] };
#pragma unroll
            for (int dp = 0; dp < 5; dp++) {
                const uint32_t voff = (uint32_t)((kc2 * 16 + vk) * AP + dp * 16 + vd) * 2;
                uint32_t bh0, bh1, bh2, bh3, bl0, bl1, bl2, bl3;
                ldm_x4_t(sb + SV_HI * 2 + voff, bh0, bh1, bh2, bh3);
                ldm_x4_t(sb + SV_LO * 2 + voff, bl0, bl1, bl2, bl3);
                mma_bf16(of[2*dp],   aH, bh0, bh1);
                mma_bf16(of[2*dp+1], aH, bh2, bh3);
                mma_bf16(of[2*dp],   aH, bl0, bl1);
                mma_bf16(of[2*dp+1], aH, bl2, bl3);
                mma_bf16(of[2*dp],   aL, bh0, bh1);
                mma_bf16(of[2*dp+1], aL, bh2, bh3);
            }
        }

        __syncthreads();               // done reading K/V smem
        if (kb + 1 < ntiles) {
            loadKV(kb + 1);
            cp_commit(); cp_wait<0>();
        }
        __syncthreads();
    }

    // ---- epilogue: normalize, split hi/lo, store bf16 ----
    const float iA = 1.f / lA, iB = 1.f / lB;
    const int gA = q0 + w * 16 + (lane >> 2);
    const int colb = h * HD + clb;
#pragma unroll
    for (int nt = 0; nt < 10; nt++) {
        const int col = colb + nt * 8;
        float v0 = of[nt][0] * iA, v1 = of[nt][1] * iA;
        float v2 = of[nt][2] * iB, v3 = of[nt][3] * iB;
        __nv_bfloat16 h0 = __float2bfloat16(v0), h1 = __float2bfloat16(v1);
        __nv_bfloat16 h2 = __float2bfloat16(v2), h3 = __float2bfloat16(v3);
        *(uint32_t*)(ohi + (size_t)gA * DIMS + col)       = pkbf(h0, h1);
        *(uint32_t*)(ohi + (size_t)(gA + 8) * DIMS + col) = pkbf(h2, h3);
        *(uint32_t*)(olo + (size_t)gA * DIMS + col)       =
            pkbf(__float2bfloat16(v0 - __bfloat162float(h0)),
                 __float2bfloat16(v1 - __bfloat162float(h1)));
        *(uint32_t*)(olo + (size_t)(gA + 8) * DIMS + col) =
            pkbf(__float2bfloat16(v2 - __bfloat162float(h2)),
                 __float2bfloat16(v3 - __bfloat162float(h3)));
    }
}

// ============================================================================
extern "C" void kernel_launch(void* const* d_in, const int* in_sizes, int n_in,
                              void* d_out, int out_size)
{
    const float* x       = (const float*)d_in[0];
    const float* Wqkv_w  = (const float*)d_in[1];
    const float* Wqkv_b  = (const float*)d_in[2];
    const float* out_w   = (const float*)d_in[3];
    const float* out_b   = (const float*)d_in[4];
    // d_in[5] = mask: causal triu(-1e9), implemented structurally; unused.
    float* outp = (float*)d_out;

    float *qkv_ptr = nullptr;
    __nv_bfloat16 *xhi, *xlo, *w1hi, *w1lo, *w2hi, *w2lo, *ahi, *alo, *qvh, *qvl;
    cudaGetSymbolAddress((void**)&qkv_ptr, g_qkv);
    cudaGetSymbolAddress((void**)&xhi,  g_xhi);   cudaGetSymbolAddress((void**)&xlo,  g_xlo);
    cudaGetSymbolAddress((void**)&w1hi, g_w1hi);  cudaGetSymbolAddress((void**)&w1lo, g_w1lo);
    cudaGetSymbolAddress((void**)&w2hi, g_w2hi);  cudaGetSymbolAddress((void**)&w2lo, g_w2lo);
    cudaGetSymbolAddress((void**)&ahi,  g_ahi);   cudaGetSymbolAddress((void**)&alo,  g_alo);
    cudaGetSymbolAddress((void**)&qvh,  g_qkvhi); cudaGetSymbolAddress((void**)&qvl,  g_qkvlo);

    cudaFuncSetAttribute(gemm_bf16x3,
                         cudaFuncAttributeMaxDynamicSharedMemorySize, GM_SMEM);
    cudaFuncSetAttribute(attn_tc,
                         cudaFuncAttributeMaxDynamicSharedMemorySize, ATT_SMEM);

    // 0) split-precision conversions of x and weights
    {
        int n4 = (SEQ * DIMS) / 4;
        cvt_hilo_kernel<<<(n4 + 255) / 256, 256>>>(x, xhi, xlo, n4);
        n4 = (QKV_N * DIMS) / 4;
        cvt_hilo_kernel<<<(n4 + 255) / 256, 256>>>(Wqkv_w, w1hi, w1lo, n4);
        n4 = (DIMS * DIMS) / 4;
        cvt_hilo_kernel<<<(n4 + 255) / 256, 256>>>(out_w, w2hi, w2lo, n4);
    }
    // 1) QKV projection (bf16x3 tensor cores) -> fp32 qkv
    {
        dim3 grid(QKV_N / GBN, SEQ / GBM);
        gemm_bf16x3<<<grid, 256, GM_SMEM>>>(xhi, xlo, w1hi, w1lo,
                                            Wqkv_b, qkv_ptr, SEQ, QKV_N, DIMS);
    }
    // 2) RoPE on q,k (fp32, in place)
    {
        int total = SEQ * NH * 16;
        rope_kernel<<<(total + 255) / 256, 256>>>(qkv_ptr);
    }
    // 3) qkv -> bf16 hi/lo
    {
        int n4 = (SEQ * QKV_N) / 4;
        cvt_hilo_kernel<<<(n4 + 255) / 256, 256>>>(qkv_ptr, qvh, qvl, n4);
    }
    // 4) tensor-core causal flash attention -> bf16 hi/lo attn out
    {
        dim3 grid(NH, SEQ / 64);
        attn_tc<<<grid, 128, ATT_SMEM>>>(qvh, qvl, ahi, alo);
    }
    // 5) output projection (bf16x3 tensor cores)
    {
        dim3 grid(DIMS / GBN, SEQ / GBM);
        gemm_bf16x3<<<grid, 256, GM_SMEM>>>(ahi, alo, w2hi, w2lo,
                                            out_b, outp, SEQ, DIMS, DIMS);
    }
}

// round 7
// speedup vs baseline: 2.9820x; 1.0444x over previous
#include <cuda_runtime.h>
#include <cuda_bf16.h>
#include <math.h>
#include <stdint.h>

#define DIMS   2560
#define NH     32
#define HD     80
#define SEQ    2048
#define QKV_N  (3*DIMS)

// ---------------- scratch (static device globals; no runtime allocation) ----
__device__ float g_qkv [SEQ * QKV_N];          // [t][3*DIMS]  q|k|v (fp32)

__device__ __nv_bfloat16 g_xhi [SEQ * DIMS];
__device__ __nv_bfloat16 g_xlo [SEQ * DIMS];
__device__ __nv_bfloat16 g_w1hi[QKV_N * DIMS];
__device__ __nv_bfloat16 g_w1lo[QKV_N * DIMS];
__device__ __nv_bfloat16 g_w2hi[DIMS * DIMS];
__device__ __nv_bfloat16 g_w2lo[DIMS * DIMS];
__device__ __nv_bfloat16 g_ahi [SEQ * DIMS];   // attention out hi/lo (bf16)
__device__ __nv_bfloat16 g_alo [SEQ * DIMS];
__device__ __nv_bfloat16 g_qkvhi[SEQ * QKV_N]; // post-rope qkv hi/lo (bf16)
__device__ __nv_bfloat16 g_qkvlo[SEQ * QKV_N];

// ============================================================================
// fp32 -> bf16 hi/lo split conversion (vectorized, memory bound)
// ============================================================================
__global__ void cvt_hilo_kernel(const float* __restrict__ src,
                                __nv_bfloat16* __restrict__ hi,
                                __nv_bfloat16* __restrict__ lo, int n4)
{
    int i = blockIdx.x * blockDim.x + threadIdx.x;
    if (i >= n4) return;
    float4 v = ((const float4*)src)[i];
    union { __nv_bfloat16 b[4]; uint2 u; } H, L;
    H.b[0] = __float2bfloat16(v.x); L.b[0] = __float2bfloat16(v.x - __bfloat162float(H.b[0]));
    H.b[1] = __float2bfloat16(v.y); L.b[1] = __float2bfloat16(v.y - __bfloat162float(H.b[1]));
    H.b[2] = __float2bfloat16(v.z); L.b[2] = __float2bfloat16(v.z - __bfloat162float(H.b[2]));
    H.b[3] = __float2bfloat16(v.w); L.b[3] = __float2bfloat16(v.w - __bfloat162float(H.b[3]));
    ((uint2*)hi)[i] = H.u;
    ((uint2*)lo)[i] = L.u;
}

// ============================================================================
// PTX helpers (all baseline compute_103-safe: sm_80-era instructions)
// ============================================================================
__device__ __forceinline__ uint32_t smem_u32(const void* p){
    uint32_t a;
    asm("{ .reg .u64 t; cvta.to.shared.u64 t, %1; cvt.u32.u64 %0, t; }"
        : "=r"(a) : "l"(p));
    return a;
}
__device__ __forceinline__ void cp16(uint32_t dst, const void* src){
    asm volatile("cp.async.ca.shared.global [%0], [%1], 16;"
                 :: "r"(dst), "l"(src) : "memory");
}
__device__ __forceinline__ void cp_commit(){
    asm volatile("cp.async.commit_group;" ::: "memory");
}
template<int N> __device__ __forceinline__ void cp_wait(){
    asm volatile("cp.async.wait_group %0;" :: "n"(N) : "memory");
}
__device__ __forceinline__ void ldm_x4(uint32_t a, uint32_t& r0, uint32_t& r1,
                                       uint32_t& r2, uint32_t& r3){
    asm volatile("ldmatrix.sync.aligned.m8n8.x4.shared.b16 {%0,%1,%2,%3}, [%4];"
                 : "=r"(r0), "=r"(r1), "=r"(r2), "=r"(r3) : "r"(a));
}
__device__ __forceinline__ void ldm_x4_t(uint32_t a, uint32_t& r0, uint32_t& r1,
                                         uint32_t& r2, uint32_t& r3){
    asm volatile("ldmatrix.sync.aligned.m8n8.x4.trans.shared.b16 {%0,%1,%2,%3}, [%4];"
                 : "=r"(r0), "=r"(r1), "=r"(r2), "=r"(r3) : "r"(a));
}
__device__ __forceinline__ void mma_bf16(float* c, const uint32_t* a,
                                         uint32_t b0, uint32_t b1){
    asm volatile(
      "mma.sync.aligned.m16n8k16.row.col.f32.bf16.bf16.f32 "
      "{%0,%1,%2,%3}, {%4,%5,%6,%7}, {%8,%9}, {%0,%1,%2,%3};"
      : "+f"(c[0]), "+f"(c[1]), "+f"(c[2]), "+f"(c[3])
      : "r"(a[0]), "r"(a[1]), "r"(a[2]), "r"(a[3]), "r"(b0), "r"(b1));
}
__device__ __forceinline__ uint32_t pkbf(__nv_bfloat16 a, __nv_bfloat16 b){
    union { __nv_bfloat16 h[2]; uint32_t u; } t;
    t.h[0] = a; t.h[1] = b;
    return t.u;
}

// ============================================================================
// bf16x3 tensor-core GEMM:  C[M,N] = A[M,K] @ B[N,K]^T + bias
// CTA tile 128x128, 4 warps, warp tile 64x64 (high MACs/LDS-byte), BK=32,
// cp.async double buffer, 2 CTAs/SM.
// ============================================================================
#define GBM 128
#define GBN 128
#define GBK 32
#define ROWP 40                 // bf16 units per smem row (80 bytes)
#define TILE_B (128 * ROWP * 2) // 10240 bytes per tile buffer
#define STAGE_B (4 * TILE_B)    // Ahi, Alo, Bhi, Blo
#define GM_SMEM (2 * STAGE_B)   // 81920 bytes

__global__ __launch_bounds__(128, 2) void gemm_bf16x3(
    const __nv_bfloat16* __restrict__ Ahi, const __nv_bfloat16* __restrict__ Alo,
    const __nv_bfloat16* __restrict__ Bhi, const __nv_bfloat16* __restrict__ Blo,
    const float* __restrict__ bias, float* __restrict__ C,
    int M, int N, int K)
{
    extern __shared__ __align__(16) char smem[];
    const uint32_t sb = smem_u32(smem);

    const int tid  = threadIdx.x;
    const int w    = tid >> 5;
    const int lane = tid & 31;
    const int bm   = blockIdx.y * GBM;
    const int bn   = blockIdx.x * GBN;
    const int wm   = (w & 1) * 64;       // warp M offset
    const int wn   = (w >> 1) * 64;      // warp N offset

    const __nv_bfloat16* gA_hi = Ahi + (size_t)bm * K;
    const __nv_bfloat16* gA_lo = Alo + (size_t)bm * K;
    const __nv_bfloat16* gB_hi = Bhi + (size_t)bn * K;
    const __nv_bfloat16* gB_lo = Blo + (size_t)bn * K;

    auto load_stage = [&](int s, int k0){
        const uint32_t dstb = sb + s * STAGE_B;
        const __nv_bfloat16* srcs[4] = { gA_hi, gA_lo, gB_hi, gB_lo };
#pragma unroll
        for (int t = 0; t < 4; t++) {
            const __nv_bfloat16* g = srcs[t];
            const uint32_t db = dstb + t * TILE_B;
#pragma unroll
            for (int i = 0; i < 4; i++) {
                const int idx = i * 128 + tid;
                const int row = idx >> 2;
                const int kq  = idx & 3;
                cp16(db + row * 80 + kq * 16, g + (size_t)row * K + k0 + kq * 8);
            }
        }
        cp_commit();
    };

    float acc[4][8][4];
#pragma unroll
    for (int mt = 0; mt < 4; mt++)
#pragma unroll
        for (int nt = 0; nt < 8; nt++)
#pragma unroll
            for (int r = 0; r < 4; r++) acc[mt][nt][r] = 0.f;

    const int nchunks = K / GBK;
    load_stage(0, 0);

    const int a_row  = lane & 15;
    const int a_koff = (lane >> 4) << 3;
    const int b_row  = (lane & 7) + ((lane >> 4) << 3);
    const int b_koff = ((lane >> 3) & 1) << 3;

    for (int ic = 0; ic < nchunks; ic++) {
        if (ic + 1 < nchunks) load_stage((ic + 1) & 1, (ic + 1) * GBK);
        if (ic + 1 < nchunks) cp_wait<1>(); else cp_wait<0>();
        __syncthreads();

        const uint32_t st = sb + (ic & 1) * STAGE_B;
        const uint32_t sAhi = st;
        const uint32_t sAlo = st + TILE_B;
        const uint32_t sBhi = st + 2 * TILE_B;
        const uint32_t sBlo = st + 3 * TILE_B;

#pragma unroll
        for (int ks = 0; ks < 2; ks++) {
            const int kb = ks * 16;
            uint32_t ahi[4][4], alo[4][4];
#pragma unroll
            for (int mt = 0; mt < 4; mt++) {
                const uint32_t aoff =
                    (uint32_t)((wm + mt * 16 + a_row) * 80 + (kb + a_koff) * 2);
                ldm_x4(sAhi + aoff, ahi[mt][0], ahi[mt][1], ahi[mt][2], ahi[mt][3]);
                ldm_x4(sAlo + aoff, alo[mt][0], alo[mt][1], alo[mt][2], alo[mt][3]);
            }
#pragma unroll
            for (int np = 0; np < 4; np++) {
                const uint32_t boff =
                    (uint32_t)((wn + np * 16 + b_row) * 80 + (kb + b_koff) * 2);
                uint32_t bh0, bh1, bh2, bh3, bl0, bl1, bl2, bl3;
                ldm_x4(sBhi + boff, bh0, bh1, bh2, bh3);
                ldm_x4(sBlo + boff, bl0, bl1, bl2, bl3);
#pragma unroll
                for (int mt = 0; mt < 4; mt++) {
                    mma_bf16(acc[mt][2*np],   ahi[mt], bh0, bh1);
                    mma_bf16(acc[mt][2*np+1], ahi[mt], bh2, bh3);
                    mma_bf16(acc[mt][2*np],   ahi[mt], bl0, bl1);
                    mma_bf16(acc[mt][2*np+1], ahi[mt], bl2, bl3);
                    mma_bf16(acc[mt][2*np],   alo[mt], bh0, bh1);
                    mma_bf16(acc[mt][2*np+1], alo[mt], bh2, bh3);
                }
            }
        }
        __syncthreads();
    }

    // ---- epilogue: fragment -> global + bias
#pragma unroll
    for (int mt = 0; mt < 4; mt++) {
        const int r0 = bm + wm + mt * 16 + (lane >> 2);
#pragma unroll
        for (int nt = 0; nt < 8; nt++) {
            const int col = bn + wn + nt * 8 + ((lane & 3) << 1);
            const float2 bv = *(const float2*)&bias[col];
            float2 v0 = { acc[mt][nt][0] + bv.x, acc[mt][nt][1] + bv.y };
            float2 v1 = { acc[mt][nt][2] + bv.x, acc[mt][nt][3] + bv.y };
            *(float2*)&C[(size_t)r0       * N + col] = v0;
            *(float2*)&C[(size_t)(r0 + 8) * N + col] = v1;
        }
    }
}

// ============================================================================
// RoPE on q and k (first 32 dims of each 80-dim head), in place (fp32).
// ============================================================================
__global__ void rope_kernel(float* __restrict__ qkv)
{
    int idx = blockIdx.x * blockDim.x + threadIdx.x;      // SEQ*NH*16 total
    if (idx >= SEQ * NH * 16) return;
    const int d = idx & 15;
    const int h = (idx >> 4) & 31;
    const int t = idx >> 9;

    const float freq  = __expf(-(float)d * 0.5756462732485115f); // ln(1e4)/16
    const float theta = (float)t * freq;
    float s, c;
    sincosf(theta, &s, &c);

    size_t base = (size_t)t * QKV_N + h * HD;
    {
        float x1 = qkv[base + d], x2 = qkv[base + d + 16];
        qkv[base + d]      = x1 * c - x2 * s;
        qkv[base + d + 16] = x1 * s + x2 * c;
    }
    base += DIMS;
    {
        float x1 = qkv[base + d], x2 = qkv[base + d + 16];
        qkv[base + d]      = x1 * c - x2 * s;
        qkv[base + d + 16] = x1 * s + x2 * c;
    }
}

// ============================================================================
// Tensor-core flash attention, causal, bf16x3 (round-6, known good).
// ============================================================================
#define AP     88
#define SQ_HI  0
#define SQ_LO  (64*AP)
#define SK_HI  (2*64*AP)
#define SK_LO  (3*64*AP)
#define SV_HI  (4*64*AP)
#define SV_LO  (5*64*AP)
#define ATT_SMEM (6*64*AP*2)   // 67584 bytes

__global__ __launch_bounds__(128, 2) void attn_tc(
    const __nv_bfloat16* __restrict__ qkvhi,
    const __nv_bfloat16* __restrict__ qkvlo,
    __nv_bfloat16* __restrict__ ohi,
    __nv_bfloat16* __restrict__ olo)
{
    extern __shared__ __align__(16) __nv_bfloat16 smA[];
    const uint32_t sb = smem_u32(smA);
    const int h = blockIdx.x, qb = blockIdx.y;
    const int tid = threadIdx.x, lane = tid & 31, w = tid >> 5;
    const int q0 = qb * 64;
    const float scale = 0.11180339887498949f;   // 1/sqrt(80)

    {
        const size_t off = (size_t)q0 * QKV_N + h * HD;
#pragma unroll
        for (int it = 0; it < 5; it++) {
            const int idx = it * 128 + tid;
            const int row = idx / 10, col = idx % 10;
            const size_t go = off + (size_t)row * QKV_N + col * 8;
            cp16(sb + (SQ_HI + row * AP) * 2 + col * 16, qkvhi + go);
            cp16(sb + (SQ_LO + row * AP) * 2 + col * 16, qkvlo + go);
        }
    }
    auto loadKV = [&](int kb){
        const size_t koff = (size_t)(kb * 64) * QKV_N + DIMS + h * HD;
#pragma unroll
        for (int it = 0; it < 5; it++) {
            const int idx = it * 128 + tid;
            const int row = idx / 10, col = idx % 10;
            const size_t gk = koff + (size_t)row * QKV_N + col * 8;
            const size_t gv = gk + DIMS;
            cp16(sb + (SK_HI + row * AP) * 2 + col * 16, qkvhi + gk);
            cp16(sb + (SK_LO + row * AP) * 2 + col * 16, qkvlo + gk);
            cp16(sb + (SV_HI + row * AP) * 2 + col * 16, qkvhi + gv);
            cp16(sb + (SV_LO + row * AP) * 2 + col * 16, qkvlo + gv);
        }
    };

    float of[10][4];
#pragma unroll
    for (int i = 0; i < 10; i++)
#pragma unroll
        for (int j = 0; j < 4; j++) of[i][j] = 0.f;
    float mA = -1e30f, mB = -1e30f, lA = 0.f, lB = 0.f;

    loadKV(0);
    cp_commit(); cp_wait<0>();
    __syncthreads();

    const int a_row  = lane & 15;
    const int a_k    = (lane >> 4) << 3;
    const int b_row  = (lane & 7) + ((lane >> 4) << 3);
    const int b_k    = ((lane >> 3) & 1) << 3;
    const int vk     = (lane & 7) + (((lane >> 3) & 1) << 3);
    const int vd     = (lane >> 4) << 3;
    const int clb    = 2 * (lane & 3);
    const int rl     = w * 16 + (lane >> 2);

    const int ntiles = qb + 1;
    for (int kb = 0; kb < ntiles; kb++) {
        float sf[8][4];
#pragma unroll
        for (int i = 0; i < 8; i++)
#pragma unroll
            for (int j = 0; j < 4; j++) sf[i][j] = 0.f;

#pragma unroll
        for (int kc = 0; kc < 5; kc++) {
            uint32_t ahi[4], alo[4];
            const uint32_t aoff = (uint32_t)((w * 16 + a_row) * AP + kc * 16 + a_k) * 2;
            ldm_x4(sb + SQ_HI * 2 + aoff, ahi[0], ahi[1], ahi[2], ahi[3]);
            ldm_x4(sb + SQ_LO * 2 + aoff, alo[0], alo[1], alo[2], alo[3]);
#pragma unroll
            for (int bp = 0; bp < 4; bp++) {
                const uint32_t boff = (uint32_t)((bp * 16 + b_row) * AP + kc * 16 + b_k) * 2;
                uint32_t bh0, bh1, bh2, bh3, bl0, bl1, bl2, bl3;
                ldm_x4(sb + SK_HI * 2 + boff, bh0, bh1, bh2, bh3);
                ldm_x4(sb + SK_LO * 2 + boff, bl0, bl1, bl2, bl3);
                mma_bf16(sf[2*bp],   ahi, bh0, bh1);
                mma_bf16(sf[2*bp+1], ahi, bh2, bh3);
                mma_bf16(sf[2*bp],   ahi, bl0, bl1);
                mma_bf16(sf[2*bp+1], ahi, bl2, bl3);
                mma_bf16(sf[2*bp],   alo, bh0, bh1);
                mma_bf16(sf[2*bp+1], alo, bh2, bh3);
            }
        }

        const bool diag = (kb == qb);
#pragma unroll
        for (int nt = 0; nt < 8; nt++) {
            const int c0 = nt * 8 + clb;
#pragma unroll
            for (int j = 0; j < 2; j++) {
                float vA = sf[nt][j]     * scale;
                float vB = sf[nt][2 + j] * scale;
                if (diag) {
                    if (c0 + j > rl)     vA = -1e30f;
                    if (c0 + j > rl + 8) vB = -1e30f;
                }
                sf[nt][j] = vA; sf[nt][2 + j] = vB;
            }
        }

        float mxA = -1e30f, mxB = -1e30f;
#pragma unroll
        for (int nt = 0; nt < 8; nt++) {
            mxA = fmaxf(mxA, fmaxf(sf[nt][0], sf[nt][1]));
            mxB = fmaxf(mxB, fmaxf(sf[nt][2], sf[nt][3]));
        }
        mxA = fmaxf(mxA, __shfl_xor_sync(0xffffffffu, mxA, 1));
        mxA = fmaxf(mxA, __shfl_xor_sync(0xffffffffu, mxA, 2));
        mxB = fmaxf(mxB, __shfl_xor_sync(0xffffffffu, mxB, 1));
        mxB = fmaxf(mxB, __shfl_xor_sync(0xffffffffu, mxB, 2));
        const float mnA = fmaxf(mA, mxA), mnB = fmaxf(mB, mxB);
        const float alphaA = __expf(mA - mnA), alphaB = __expf(mB - mnB);
        mA = mnA; mB = mnB;

        float sA = 0.f, sB = 0.f;
#pragma unroll
        for (int nt = 0; nt < 8; nt++) {
#pragma unroll
            for (int j = 0; j < 2; j++) {
                float pA = __expf(sf[nt][j]     - mnA);
                float pB = __expf(sf[nt][2 + j] - mnB);
                sf[nt][j] = pA; sf[nt][2 + j] = pB;
                sA += pA; sB += pB;
            }
        }
        sA += __shfl_xor_sync(0xffffffffu, sA, 1);
        sA += __shfl_xor_sync(0xffffffffu, sA, 2);
        sB += __shfl_xor_sync(0xffffffffu, sB, 1);
        sB += __shfl_xor_sync(0xffffffffu, sB, 2);
        lA = lA * alphaA + sA;
        lB = lB * alphaB + sB;
#pragma unroll
        for (int d = 0; d < 10; d++) {
            of[d][0] *= alphaA; of[d][1] *= alphaA;
            of[d][2] *= alphaB; of[d][3] *= alphaB;
        }

#pragma unroll
        for (int kc2 = 0; kc2 < 4; kc2++) {
            uint32_t phi[4], plo[4];
#pragma unroll
            for (int half = 0; half < 2; half++) {
                const int nt = 2 * kc2 + half;
                const float v0 = sf[nt][0], v1 = sf[nt][1];
                const float v2 = sf[nt][2], v3 = sf[nt][3];
                __nv_bfloat16 h0 = __float2bfloat16(v0), h1 = __float2bfloat16(v1);
                __nv_bfloat16 h2 = __float2bfloat16(v2), h3 = __float2bfloat16(v3);
                phi[half * 2 + 0] = pkbf(h0, h1);
                phi[half * 2 + 1] = pkbf(h2, h3);
                plo[half * 2 + 0] = pkbf(__float2bfloat16(v0 - __bfloat162float(h0)),
                                         __float2bfloat16(v1 - __bfloat162float(h1)));
                plo[half * 2 + 1] = pkbf(__float2bfloat16(v2 - __bfloat162float(h2)),
                                         __float2bfloat16(v3 - __bfloat162float(h3)));
            }
            uint32_t aH[4] = { phi[0], phi[1], phi[2], phi[3] };
            uint32_t aL[4] = { plo[0], plo[1], plo[2], plo[3] };
#pragma unroll
            for (int dp = 0; dp < 5; dp++) {
                const uint32_t voff = (uint32_t)((kc2 * 16 + vk) * AP + dp * 16 + vd) * 2;
                uint32_t bh0, bh1, bh2, bh3, bl0, bl1, bl2, bl3;
                ldm_x4_t(sb + SV_HI * 2 + voff, bh0, bh1, bh2, bh3);
                ldm_x4_t(sb + SV_LO * 2 + voff, bl0, bl1, bl2, bl3);
                mma_bf16(of[2*dp],   aH, bh0, bh1);
                mma_bf16(of[2*dp+1], aH, bh2, bh3);
                mma_bf16(of[2*dp],   aH, bl0, bl1);
                mma_bf16(of[2*dp+1], aH, bl2, bl3);
                mma_bf16(of[2*dp],   aL, bh0, bh1);
                mma_bf16(of[2*dp+1], aL, bh2, bh3);
            }
        }

        __syncthreads();
        if (kb + 1 < ntiles) {
            loadKV(kb + 1);
            cp_commit(); cp_wait<0>();
        }
        __syncthreads();
    }

    const float iA = 1.f / lA, iB = 1.f / lB;
    const int gA = q0 + w * 16 + (lane >> 2);
    const int colb = h * HD + clb;
#pragma unroll
    for (int nt = 0; nt < 10; nt++) {
        const int col = colb + nt * 8;
        float v0 = of[nt][0] * iA, v1 = of[nt][1] * iA;
        float v2 = of[nt][2] * iB, v3 = of[nt][3] * iB;
        __nv_bfloat16 h0 = __float2bfloat16(v0), h1 = __float2bfloat16(v1);
        __nv_bfloat16 h2 = __float2bfloat16(v2), h3 = __float2bfloat16(v3);
        *(uint32_t*)(ohi + (size_t)gA * DIMS + col)       = pkbf(h0, h1);
        *(uint32_t*)(ohi + (size_t)(gA + 8) * DIMS + col) = pkbf(h2, h3);
        *(uint32_t*)(olo + (size_t)gA * DIMS + col)       =
            pkbf(__float2bfloat16(v0 - __bfloat162float(h0)),
                 __float2bfloat16(v1 - __bfloat162float(h1)));
        *(uint32_t*)(olo + (size_t)(gA + 8) * DIMS + col) =
            pkbf(__float2bfloat16(v2 - __bfloat162float(h2)),
                 __float2bfloat16(v3 - __bfloat162float(h3)));
    }
}

// ============================================================================
extern "C" void kernel_launch(void* const* d_in, const int* in_sizes, int n_in,
                              void* d_out, int out_size)
{
    const float* x       = (const float*)d_in[0];
    const float* Wqkv_w  = (const float*)d_in[1];
    const float* Wqkv_b  = (const float*)d_in[2];
    const float* out_w   = (const float*)d_in[3];
    const float* out_b   = (const float*)d_in[4];
    // d_in[5] = mask: causal triu(-1e9), implemented structurally; unused.
    float* outp = (float*)d_out;

    float *qkv_ptr = nullptr;
    __nv_bfloat16 *xhi, *xlo, *w1hi, *w1lo, *w2hi, *w2lo, *ahi, *alo, *qvh, *qvl;
    cudaGetSymbolAddress((void**)&qkv_ptr, g_qkv);
    cudaGetSymbolAddress((void**)&xhi,  g_xhi);   cudaGetSymbolAddress((void**)&xlo,  g_xlo);
    cudaGetSymbolAddress((void**)&w1hi, g_w1hi);  cudaGetSymbolAddress((void**)&w1lo, g_w1lo);
    cudaGetSymbolAddress((void**)&w2hi, g_w2hi);  cudaGetSymbolAddress((void**)&w2lo, g_w2lo);
    cudaGetSymbolAddress((void**)&ahi,  g_ahi);   cudaGetSymbolAddress((void**)&alo,  g_alo);
    cudaGetSymbolAddress((void**)&qvh,  g_qkvhi); cudaGetSymbolAddress((void**)&qvl,  g_qkvlo);

    cudaFuncSetAttribute(gemm_bf16x3,
                         cudaFuncAttributeMaxDynamicSharedMemorySize, GM_SMEM);
    cudaFuncSetAttribute(attn_tc,
                         cudaFuncAttributeMaxDynamicSharedMemorySize, ATT_SMEM);

    // 0) split-precision conversions of x and weights
    {
        int n4 = (SEQ * DIMS) / 4;
        cvt_hilo_kernel<<<(n4 + 255) / 256, 256>>>(x, xhi, xlo, n4);
        n4 = (QKV_N * DIMS) / 4;
        cvt_hilo_kernel<<<(n4 + 255) / 256, 256>>>(Wqkv_w, w1hi, w1lo, n4);
        n4 = (DIMS * DIMS) / 4;
        cvt_hilo_kernel<<<(n4 + 255) / 256, 256>>>(out_w, w2hi, w2lo, n4);
    }
    // 1) QKV projection (bf16x3 tensor cores) -> fp32 qkv
    {
        dim3 grid(QKV_N / GBN, SEQ / GBM);
        gemm_bf16x3<<<grid, 128, GM_SMEM>>>(xhi, xlo, w1hi, w1lo,
                                            Wqkv_b, qkv_ptr, SEQ, QKV_N, DIMS);
    }
    // 2) RoPE on q,k (fp32, in place)
    {
        int total = SEQ * NH * 16;
        rope_kernel<<<(total + 255) / 256, 256>>>(qkv_ptr);
    }
    // 3) qkv -> bf16 hi/lo
    {
        int n4 = (SEQ * QKV_N) / 4;
        cvt_hilo_kernel<<<(n4 + 255) / 256, 256>>>(qkv_ptr, qvh, qvl, n4);
    }
    // 4) tensor-core causal flash attention -> bf16 hi/lo attn out
    {
        dim3 grid(NH, SEQ / 64);
        attn_tc<<<grid, 128, ATT_SMEM>>>(qvh, qvl, ahi, alo);
    }
    // 5) output projection (bf16x3 tensor cores)
    {
        dim3 grid(DIMS / GBN, SEQ / GBM);
        gemm_bf16x3<<<grid, 128, GM_SMEM>>>(ahi, alo, w2hi, w2lo,
                                            out_b, outp, SEQ, DIMS, DIMS);
    }
}